// round 1
// baseline (speedup 1.0000x reference)
#include <cuda_runtime.h>
#include <math_constants.h>

// Scratch: CSR offsets for up to 65536 nodes (+1). N_NODES = 50000 here.
__device__ int g_seg_offsets[65537];

// One thread per node (plus one for the sentinel): binary-search lower_bound
// of node id n in the sorted segment_ids array.
__global__ void offsets_kernel(const int* __restrict__ seg, int E, int N) {
    int n = blockIdx.x * blockDim.x + threadIdx.x;
    if (n > N) return;
    int lo = 0, hi = E;
    while (lo < hi) {
        int mid = (lo + hi) >> 1;
        if (seg[mid] < n) lo = mid + 1; else hi = mid;
    }
    g_seg_offsets[n] = lo;
}

// One warp per node. D fixed at 48: lane holds acc0 (d = lane) and, for
// lanes 0-15, acc1 (d = 32 + lane).
__global__ void __launch_bounds__(256, 8)
gat_kernel(const float* __restrict__ a,
           const float* __restrict__ ft,
           float* __restrict__ out, int N) {
    int warp = (blockIdx.x * blockDim.x + threadIdx.x) >> 5;
    int lane = threadIdx.x & 31;
    if (warp >= N) return;

    int s = g_seg_offsets[warp];
    int t = g_seg_offsets[warp + 1];
    float* orow = out + (size_t)warp * 48;

    if (s == t) {
        // Empty segment: reference yields 0/0 handled as 0-sum -> out = 0
        orow[lane] = 0.0f;
        if (lane < 16) orow[32 + lane] = 0.0f;
        return;
    }

    // ---- Phase A: segment max (a is small; L2-resident) ----
    float m = -CUDART_INF_F;
    for (int i = s + lane; i < t; i += 32) m = fmaxf(m, a[i]);
    #pragma unroll
    for (int o = 16; o; o >>= 1) m = fmaxf(m, __shfl_xor_sync(0xffffffffu, m, o));

    // ---- Phase B: sum of exp ----
    float ssum = 0.0f;
    for (int i = s + lane; i < t; i += 32) ssum += __expf(a[i] - m);
    #pragma unroll
    for (int o = 16; o; o >>= 1) ssum += __shfl_xor_sync(0xffffffffu, ssum, o);
    float inv = 1.0f / ssum;

    // ---- Phase C: weighted feature accumulation ----
    // Chunk edges by 32: each lane computes ONE exp (one EX2 per edge total),
    // then the warp sweeps the chunk broadcasting weights via shfl while all
    // lanes do coalesced 128B+64B row loads of ft.
    float acc0 = 0.0f, acc1 = 0.0f;
    for (int base = s; base < t; base += 32) {
        int idx = base + lane;
        float w = (idx < t) ? __expf(a[idx] - m) * inv : 0.0f;
        int nk = min(32, t - base);
        const float* fp = ft + (size_t)base * 48;
        #pragma unroll 4
        for (int j = 0; j < nk; j++) {
            float wj = __shfl_sync(0xffffffffu, w, j);
            acc0 += wj * fp[lane];
            if (lane < 16) acc1 += wj * fp[32 + lane];
            fp += 48;
        }
    }

    orow[lane] = acc0;
    if (lane < 16) orow[32 + lane] = acc1;
}

extern "C" void kernel_launch(void* const* d_in, const int* in_sizes, int n_in,
                              void* d_out, int out_size) {
    const float* a   = (const float*)d_in[0];
    const float* ft  = (const float*)d_in[1];
    const int*   seg = (const int*)d_in[2];
    float* out = (float*)d_out;

    int E = in_sizes[0];
    int N = out_size / 48;   // D_FEAT = 48

    // Build CSR offsets
    {
        int threads = 256;
        int blocks = (N + 1 + threads - 1) / threads;
        offsets_kernel<<<blocks, threads>>>(seg, E, N);
    }

    // One warp per node, 8 warps per block
    {
        int threads = 256;
        int warps_per_block = threads / 32;
        int blocks = (N + warps_per_block - 1) / warps_per_block;
        gat_kernel<<<blocks, threads>>>(a, ft, out, N);
    }
}